// round 1
// baseline (speedup 1.0000x reference)
#include <cuda_runtime.h>

// ----------------------------------------------------------------------------
// Opportunistic-policy energy state machine, exact float32 sequential replay.
//
// Semantics replicated bit-for-bit from the JAX scan:
//   e_norm = min(max((e_prev + h) - L, 0), 4*thresh)
//   wake  (off, e >= 5L+OH):  next step preset e = e - OH, decision skipped
//   send  (on,  e >= thresh+5L): next P steps e = (base - lin[j]) + h,
//                                lin[j] = fl(fl(thresh*(j+1))/P)
//   breaks at array edges -> trailing zeros (handled by zero-fill kernel)
//
// All float adds use __fadd_rn to pin JAX's left-associated rounding and
// forbid FMA contraction. fminf/fmaxf == jnp.clip exactly (no NaNs here).
// ----------------------------------------------------------------------------

static __global__ void fill_zero_kernel(float* __restrict__ out, int n) {
    int i = blockIdx.x * blockDim.x + threadIdx.x;
    if (i < n) out[i] = 0.0f;
}

#define CHUNK 16

static __global__ void __launch_bounds__(32, 1) sim_kernel(
    const float* __restrict__ h,
    const float* __restrict__ pL,
    const float* __restrict__ pOH,
    const float* __restrict__ pTH,
    const void*  pP_raw,
    float* __restrict__ e_trace,
    float* __restrict__ actions,
    int n, int write_actions)
{
    if (threadIdx.x != 0 || blockIdx.x != 0) return;

    const float L  = *pL;
    const float OH = *pOH;
    const float TH = *pTH;

    int P = 8;
    if (pP_raw) {
        int pi = *(const int*)pP_raw;
        if (pi >= 1 && pi <= 1024) {
            P = pi;
        } else {
            float pf = *(const float*)pP_raw;   // defensive: scalar may be f32
            if (pf >= 1.0f && pf <= 1024.0f) P = (int)pf;
        }
    }

    const float MAXE   = __fmul_rn(4.0f, TH);
    const float fiveL  = __fmul_rn(5.0f, L);
    const float wakeTH = __fadd_rn(fiveL, OH);   // 5L + OH
    const float sendTH = __fadd_rn(TH, fiveL);   // thresh + 5L
    const float Pf     = (float)P;

    float e        = 0.0f;   // e_trace[0]
    bool  on       = false;
    int   send_rem = 0;
    float send_base= 0.0f;
    bool  preset   = false;
    float pv       = 0.0f;
    bool  done     = false;

    // Double-buffered register prefetch queue: 16 independent LDGs in flight
    // while the 16-step dependent FADD chain (~256 cyc) runs -> load latency
    // fully hidden behind compute.
    float cur[CHUNK], nxt[CHUNK];
    int base = 1;
    #pragma unroll
    for (int u = 0; u < CHUNK; u++)
        cur[u] = (base + u < n) ? h[base + u] : 0.0f;

    while (base < n && !done) {
        const int nb = base + CHUNK;
        #pragma unroll
        for (int u = 0; u < CHUNK; u++)
            nxt[u] = (nb + u < n) ? h[nb + u] : 0.0f;

        const int lim = (n - base < CHUNK) ? (n - base) : CHUNK;

        #pragma unroll
        for (int u = 0; u < CHUNK; u++) {
            if (u >= lim || done) break;
            const int   t  = base + u;
            const float hv = cur[u];

            float e_t;
            bool  action = false;

            if (preset) {
                // wake preset step: e[k+1] = e_k - OH, decision skipped
                e_t = pv;
                preset = false;
            } else if (send_rem > 0) {
                // packet transmission step (no clip, from fixed base)
                const int   j   = P - send_rem;                       // 0..P-1
                const float lin = __fdiv_rn(__fmul_rn(TH, (float)(j + 1)), Pf);
                e_t = __fadd_rn(__fadd_rn(send_base, -lin), hv);
                send_rem--;
            } else {
                // normal charging recurrence + decision
                e_t = fminf(fmaxf(__fadd_rn(__fadd_rn(e, hv), -L), 0.0f), MAXE);
                if (!on) {
                    if (e_t >= wakeTH) {
                        if (t + 1 >= n) {
                            done = true;              // wake_break
                        } else {
                            on = true;
                            preset = true;
                            pv = __fadd_rn(e_t, -OH);
                        }
                    }
                } else {
                    if (e_t == 0.0f) {
                        on = false;                   // off event
                    } else if (e_t >= sendTH) {
                        if (t + P + 1 >= n) {
                            done = true;              // send_break
                        } else {
                            send_rem  = P;
                            send_base = e_t;
                            action    = true;
                        }
                    }
                }
            }

            e = e_t;
            e_trace[t] = e_t;                          // break step still outputs e_t
            if (action && write_actions) actions[t] = 1.0f;
        }

        #pragma unroll
        for (int u = 0; u < CHUNK; u++) cur[u] = nxt[u];
        base = nb;
    }
    // tail after 'done' stays zero (pre-filled)
}

extern "C" void kernel_launch(void* const* d_in, const int* in_sizes, int n_in,
                              void* d_out, int out_size) {
    const float* h   = (const float*)d_in[0];
    const float* pL  = (const float*)d_in[1];
    const float* pOH = (const float*)d_in[2];
    const float* pTH = (const float*)d_in[3];
    const void*  pP  = (n_in >= 5) ? d_in[4] : nullptr;
    const int    n   = in_sizes[0];

    float* out = (float*)d_out;
    const int write_actions = (out_size >= 2 * n) ? 1 : 0;
    float* actions = out + n;

    // Zero-fill: covers t=0, all 'false' actions, and any post-break tail.
    const int threads = 256;
    const int blocks  = (out_size + threads - 1) / threads;
    fill_zero_kernel<<<blocks, threads>>>(out, out_size);

    // Exact sequential state-machine walk (single thread, prefetch-pipelined).
    sim_kernel<<<1, 32>>>(h, pL, pOH, pTH, pP, out, actions, n, write_actions);
}

// round 2
// speedup vs baseline: 3.0352x; 3.0352x over previous
#include <cuda_runtime.h>

// ----------------------------------------------------------------------------
// Opportunistic-policy energy state machine, exact float32 sequential replay.
//
// Fast/slow split:
//   FAST (common): e'' = rn(rn(e+h) - L) with NO clamps, valid & bit-exact
//     whenever 0 < e'' < min(stateThresh, MAXE). A range trigger
//     (e'' <= 0 || e'' >= trigHi) catches every step where a clamp could bind
//     OR an event (wake / off / send) could fire, and falls to the slow path.
//   SLOW (rare):  full exact semantics (clips, wake preset, P-step packet,
//     boundary breaks) — identical to the Round-1 kernel that scored
//     rel_err = 0.0.
//
// All rounding pinned: fma(x, 1.0f, y) == __fadd_rn(x, y) bit-exactly
// (single rounding, exact *1.0), __fdiv_rn for lin[], fminf/fmaxf == jnp.clip.
// ----------------------------------------------------------------------------

static __global__ void fill_zero_kernel(float* __restrict__ out, int n) {
    int i = blockIdx.x * blockDim.x + threadIdx.x;
    if (i < n) out[i] = 0.0f;
}

// rn(a + c) via FFMA with immediate 1.0 multiplier (rt 1 vs FADD rt 2).
__device__ __forceinline__ float addrn(float a, float c) {
    float r;
    asm("fma.rn.f32 %0, %1, 0f3F800000, %2;" : "=f"(r) : "f"(a), "f"(c));
    return r;
}

static __global__ void __launch_bounds__(32, 1) sim_kernel(
    const float* __restrict__ h,
    const float* __restrict__ pL,
    const float* __restrict__ pOH,
    const float* __restrict__ pTH,
    const void*  pP_raw,
    float* __restrict__ e_trace,
    float* __restrict__ actions,
    int n, int write_actions)
{
    if (threadIdx.x != 0 || blockIdx.x != 0) return;

    const float L  = *pL;
    const float OH = *pOH;
    const float TH = *pTH;

    int P = 8;
    if (pP_raw) {
        int pi = *(const int*)pP_raw;
        if (pi >= 1 && pi <= 1024) {
            P = pi;
        } else {
            float pf = *(const float*)pP_raw;
            if (pf >= 1.0f && pf <= 1024.0f) P = (int)pf;
        }
    }

    const float MAXE   = __fmul_rn(4.0f, TH);
    const float fiveL  = __fmul_rn(5.0f, L);
    const float wakeTH = __fadd_rn(fiveL, OH);   // 5L + OH
    const float sendTH = __fadd_rn(TH, fiveL);   // thresh + 5L
    const float Pf     = (float)P;
    const float negL   = -L;

    float e        = 0.0f;   // e_trace[0]
    bool  on       = false;
    int   send_rem = 0;
    float send_base= 0.0f;
    bool  preset   = false;
    float pv       = 0.0f;
    bool  done     = false;
    int   force    = 0;      // scalar steps forced after a vector trigger
    int   t        = 1;

    while (!done && t < n) {
        // ------------------------------------------------------------------
        // SCALAR exact step (slow path / realign / tail / forced progress)
        // ------------------------------------------------------------------
        if (force > 0 || preset || send_rem > 0 || (t & 3) != 0 || t + 32 > n) {
            if (force > 0) force--;
            const float hv = h[t];
            float e_t;
            bool  action = false;

            if (preset) {
                e_t = pv;                            // wake preset, no decision
                preset = false;
            } else if (send_rem > 0) {
                const int   j   = P - send_rem;      // 0..P-1
                const float lin = __fdiv_rn(__fmul_rn(TH, (float)(j + 1)), Pf);
                e_t = __fadd_rn(__fadd_rn(send_base, -lin), hv);
                send_rem--;
            } else {
                e_t = fminf(fmaxf(__fadd_rn(__fadd_rn(e, hv), -L), 0.0f), MAXE);
                if (!on) {
                    if (e_t >= wakeTH) {
                        if (t + 1 >= n) done = true;           // wake_break
                        else { on = true; preset = true; pv = __fadd_rn(e_t, -OH); }
                    }
                } else {
                    if (e_t == 0.0f) on = false;               // off event
                    else if (e_t >= sendTH) {
                        if (t + P + 1 >= n) done = true;       // send_break
                        else { send_rem = P; send_base = e_t; action = true; }
                    }
                }
            }

            e = e_t;
            e_trace[t] = e_t;
            if (action && write_actions) actions[t] = 1.0f;
            t++;
            continue;
        }

        // ------------------------------------------------------------------
        // VECTOR fast phase: t % 4 == 0, t + 32 <= n, no pending preset/send.
        // Clamp-free chain, range-triggered bail-out. Processes 32 steps per
        // iteration with double-buffered float4 loads + L2 prefetch.
        // ------------------------------------------------------------------
        const float th = fminf(on ? sendTH : wakeTH, MAXE);  // trigger bound

        float4 c[8];
        {
            const float4* p = reinterpret_cast<const float4*>(h + t);
            #pragma unroll
            for (int i = 0; i < 8; i++) c[i] = __ldg(p + i);
        }

        bool trig = false;
        for (;;) {
            const bool have_next = (t + 64 <= n);
            float4 nx[8];
            if (have_next) {
                const float4* p = reinterpret_cast<const float4*>(h + t + 32);
                #pragma unroll
                for (int i = 0; i < 8; i++) nx[i] = __ldg(p + i);
            }
            if (t + 4096 < n)
                asm volatile("prefetch.global.L2 [%0];" :: "l"(h + t + 4096));

            #pragma unroll
            for (int g = 0; g < 8; g++) {
                const float  es = e;
                const float4 hv = c[g];
                const float e0 = addrn(addrn(hv.x, es), negL);
                const float e1 = addrn(addrn(hv.y, e0), negL);
                const float e2 = addrn(addrn(hv.z, e1), negL);
                const float e3 = addrn(addrn(hv.w, e2), negL);
                const bool bad =
                    (e0 <= 0.0f) | (e0 >= th) |
                    (e1 <= 0.0f) | (e1 >= th) |
                    (e2 <= 0.0f) | (e2 >= th) |
                    (e3 <= 0.0f) | (e3 >= th);
                if (bad) { e = es; trig = true; break; }
                *reinterpret_cast<float4*>(e_trace + t) = make_float4(e0, e1, e2, e3);
                e = e3;
                t += 4;
            }

            if (trig || !have_next) break;
            #pragma unroll
            for (int i = 0; i < 8; i++) c[i] = nx[i];
        }

        if (trig) force = 4;   // guarantee scalar progress past the trigger
        // tail (< 32 remaining) is picked up by the scalar branch above
    }
    // post-'done' tail stays zero (pre-filled)
}

extern "C" void kernel_launch(void* const* d_in, const int* in_sizes, int n_in,
                              void* d_out, int out_size) {
    const float* h   = (const float*)d_in[0];
    const float* pL  = (const float*)d_in[1];
    const float* pOH = (const float*)d_in[2];
    const float* pTH = (const float*)d_in[3];
    const void*  pP  = (n_in >= 5) ? d_in[4] : nullptr;
    const int    n   = in_sizes[0];

    float* out = (float*)d_out;
    const int write_actions = (out_size >= 2 * n) ? 1 : 0;
    float* actions = out + n;

    const int threads = 256;
    const int blocks  = (out_size + threads - 1) / threads;
    fill_zero_kernel<<<blocks, threads>>>(out, out_size);

    sim_kernel<<<1, 32>>>(h, pL, pOH, pTH, pP, out, actions, n, write_actions);
}